// round 1
// baseline (speedup 1.0000x reference)
#include <cuda_runtime.h>
#include <cuda_fp16.h>
#include <cstdint>

// SplineGCN: out[n] = mean_{e: row(e)=n} sum_s w_s(e) * (feat[col(e)] @ W[flat_s(e)]) + bias
// Plan:
//   K0: zero out + deg
//   K1: permute W -> half2-packed B for mma.sync (g_Bperm)
//   K2: Z[n, k*32+o] = feat @ W  via m16n8k16 fp16 mma, fp16 output, smem-staged coalesced stores
//   K3: per-edge trilinear gather of 8 Z rows (corner pairs are contiguous 128B), fp32 combine,
//       red.global.add.v4.f32 scatter into out, deg count
//   K4: out = out / max(deg,1) + bias

#define MAXN 50176
#define KO 2048              // 64 kernels * 32 out
#define BROW_STRIDE 2056     // 2048 + 8 pad (u32) -> row stride 8224B == 32 mod 128 (bank-conflict-free B frags)
#define CPITCH 36            // C staging pitch in u32 (144B) -> conflict-free STS/LDS

__device__ __half   g_Z[(size_t)MAXN * KO];   // ~205 MB fp16 scratch
__device__ uint32_t g_Bperm[16 * KO];         // half2-packed weights: (B[2kk][c], B[2kk+1][c])
__device__ float    g_deg[MAXN];

static __device__ __forceinline__ uint32_t h2u(__half2 h) {
    return *reinterpret_cast<uint32_t*>(&h);
}

__global__ void zero_kernel(float* __restrict__ out, int n) {
    int i = blockIdx.x * blockDim.x + threadIdx.x;
    if (i < n * 32) out[i] = 0.0f;
    if (i < n) g_deg[i] = 0.0f;
}

// Bperm[kk*2048 + c] packs weight rows (2kk, 2kk+1) of column c = k*32 + o.
__global__ void prep_kernel(const float* __restrict__ w) {
    int i = blockIdx.x * blockDim.x + threadIdx.x;
    if (i >= 16 * KO) return;
    int kk = i >> 11, c = i & 2047;
    int k = c >> 5, o = c & 31;
    float w0 = w[k * 1024 + (2 * kk) * 32 + o];
    float w1 = w[k * 1024 + (2 * kk + 1) * 32 + o];
    g_Bperm[i] = h2u(__floats2half2_rn(w0, w1));
}

static __device__ __forceinline__ uint32_t lda(const float* __restrict__ f, int r, int c, int n) {
    if (r >= n) return 0u;
    float2 v = *reinterpret_cast<const float2*>(f + (size_t)r * 32 + c);
    return h2u(__floats2half2_rn(v.x, v.y));
}

// Z = feat[N,32] @ B[32,2048], fp16 out. 256 threads, 8 warps, 16 rows/warp, full B in smem.
__global__ void __launch_bounds__(256) gemm_kernel(const float* __restrict__ feat, int n) {
    extern __shared__ uint32_t smem[];
    uint32_t* sB = smem;
    for (int i = threadIdx.x; i < 16 * KO; i += blockDim.x)
        sB[(i >> 11) * BROW_STRIDE + (i & 2047)] = g_Bperm[i];
    __syncthreads();

    int warp = threadIdx.x >> 5, lane = threadIdx.x & 31;
    int g = lane >> 2, t4 = lane & 3;
    int n0 = blockIdx.x * 128 + warp * 16;
    if (n0 >= n) return;
    uint32_t* sC = smem + 16 * BROW_STRIDE + warp * (16 * CPITCH);

    int r0 = n0 + g, r1 = r0 + 8;
    uint32_t a[2][4];
#pragma unroll
    for (int ks = 0; ks < 2; ks++) {
        int c0 = ks * 16 + t4 * 2;
        a[ks][0] = lda(feat, r0, c0, n);
        a[ks][1] = lda(feat, r1, c0, n);
        a[ks][2] = lda(feat, r0, c0 + 8, n);
        a[ks][3] = lda(feat, r1, c0 + 8, n);
    }

    for (int oc = 0; oc < KO; oc += 64) {
#pragma unroll
        for (int nb = 0; nb < 8; nb++) {
            int col = oc + nb * 8 + g;
            float c0 = 0.f, c1 = 0.f, c2 = 0.f, c3 = 0.f;
#pragma unroll
            for (int ks = 0; ks < 2; ks++) {
                uint32_t b0 = sB[(ks * 8 + t4) * BROW_STRIDE + col];
                uint32_t b1 = sB[(ks * 8 + t4 + 4) * BROW_STRIDE + col];
                asm volatile(
                    "mma.sync.aligned.m16n8k16.row.col.f32.f16.f16.f32 "
                    "{%0,%1,%2,%3}, {%4,%5,%6,%7}, {%8,%9}, {%0,%1,%2,%3};"
                    : "+f"(c0), "+f"(c1), "+f"(c2), "+f"(c3)
                    : "r"(a[ks][0]), "r"(a[ks][1]), "r"(a[ks][2]), "r"(a[ks][3]),
                      "r"(b0), "r"(b1));
            }
            sC[g * CPITCH + nb * 4 + t4]       = h2u(__floats2half2_rn(c0, c1));
            sC[(g + 8) * CPITCH + nb * 4 + t4] = h2u(__floats2half2_rn(c2, c3));
        }
        __syncwarp();
#pragma unroll
        for (int p = 0; p < 4; p++) {
            int idx = p * 32 + lane;
            int ri = idx >> 3, q = idx & 7;
            int rr = n0 + ri;
            if (rr < n) {
                uint4 v = *reinterpret_cast<const uint4*>(sC + ri * CPITCH + q * 4);
                *reinterpret_cast<uint4*>(g_Z + (size_t)rr * KO + oc + q * 8) = v;
            }
        }
        __syncwarp();
    }
}

// 4 lanes per edge, each lane owns 8 output features.
__global__ void __launch_bounds__(256) edge_kernel(const float* __restrict__ pseudo,
                                                   const int* __restrict__ ei,
                                                   float* __restrict__ out, int E) {
    int t = blockIdx.x * blockDim.x + threadIdx.x;
    int e = t >> 2;
    if (e >= E) return;
    int l4 = t & 3;

    int row = ei[e];
    int col = ei[E + e];

    float v0 = pseudo[e * 3 + 0] * 3.0f;
    float v1 = pseudo[e * 3 + 1] * 3.0f;
    float v2 = pseudo[e * 3 + 2] * 3.0f;
    int b0 = (int)v0; b0 = b0 > 2 ? 2 : b0;
    int b1 = (int)v1; b1 = b1 > 2 ? 2 : b1;
    int b2 = (int)v2; b2 = b2 > 2 ? 2 : b2;
    float f0 = v0 - (float)b0, f1 = v1 - (float)b1, f2 = v2 - (float)b2;
    int base = b0 + (b1 << 2) + (b2 << 4);

    const __half* zp = g_Z + (size_t)col * KO + l4 * 8;

    float a0 = 0.f, a1 = 0.f, a2 = 0.f, a3 = 0.f, a4 = 0.f, a5 = 0.f, a6 = 0.f, a7 = 0.f;
#pragma unroll
    for (int s = 0; s < 8; s++) {
        float w = ((s & 1) ? f0 : 1.0f - f0) *
                  ((s & 2) ? f1 : 1.0f - f1) *
                  ((s & 4) ? f2 : 1.0f - f2);
        int k = base + (s & 1) + ((s & 2) << 1) + ((s & 4) << 2);
        uint4 u = *reinterpret_cast<const uint4*>(zp + (k << 5));
        float2 p0 = __half22float2(*reinterpret_cast<__half2*>(&u.x));
        float2 p1 = __half22float2(*reinterpret_cast<__half2*>(&u.y));
        float2 p2 = __half22float2(*reinterpret_cast<__half2*>(&u.z));
        float2 p3 = __half22float2(*reinterpret_cast<__half2*>(&u.w));
        a0 = fmaf(w, p0.x, a0); a1 = fmaf(w, p0.y, a1);
        a2 = fmaf(w, p1.x, a2); a3 = fmaf(w, p1.y, a3);
        a4 = fmaf(w, p2.x, a4); a5 = fmaf(w, p2.y, a5);
        a6 = fmaf(w, p3.x, a6); a7 = fmaf(w, p3.y, a7);
    }

    float* dst = out + (size_t)row * 32 + l4 * 8;
    asm volatile("red.global.add.v4.f32 [%0], {%1,%2,%3,%4};"
                 :: "l"(dst), "f"(a0), "f"(a1), "f"(a2), "f"(a3) : "memory");
    asm volatile("red.global.add.v4.f32 [%0], {%1,%2,%3,%4};"
                 :: "l"(dst + 4), "f"(a4), "f"(a5), "f"(a6), "f"(a7) : "memory");
    if (l4 == 0) atomicAdd(&g_deg[row], 1.0f);
}

__global__ void final_kernel(float* __restrict__ out, const float* __restrict__ bias, int n) {
    int i = blockIdx.x * blockDim.x + threadIdx.x;
    if (i >= n * 32) return;
    float d = g_deg[i >> 5];
    out[i] = out[i] / fmaxf(d, 1.0f) + bias[i & 31];
}

extern "C" void kernel_launch(void* const* d_in, const int* in_sizes, int n_in,
                              void* d_out, int out_size) {
    const float* feat   = (const float*)d_in[0];
    const float* pseudo = (const float*)d_in[1];
    const float* weight = (const float*)d_in[2];
    const float* bias   = (const float*)d_in[3];
    const int*   ei     = (const int*)d_in[4];
    int n = in_sizes[0] / 32;
    int E = in_sizes[4] / 2;
    float* out = (float*)d_out;

    const int smem_bytes = (16 * BROW_STRIDE + 8 * 16 * CPITCH) * 4;  // ~150 KB
    cudaFuncSetAttribute(gemm_kernel, cudaFuncAttributeMaxDynamicSharedMemorySize, smem_bytes);

    zero_kernel<<<(n * 32 + 255) / 256, 256>>>(out, n);
    prep_kernel<<<(16 * KO + 255) / 256, 256>>>(weight);
    gemm_kernel<<<(n + 127) / 128, 256, smem_bytes>>>(feat, n);
    edge_kernel<<<(E * 4 + 255) / 256, 256>>>(pseudo, ei, out, E);
    final_kernel<<<(n * 32 + 255) / 256, 256>>>(out, bias, n);
}

// round 2
// speedup vs baseline: 1.0374x; 1.0374x over previous
#include <cuda_runtime.h>
#include <cuda_fp16.h>
#include <cstdint>

// SplineGCN: out[n] = mean_{e: row(e)=n} sum_s w_s(e) * (feat[col(e)] @ W[flat_s(e)]) + bias
// Plan:
//   K0: zero out + deg
//   K1: permute W -> half2-packed B for mma.sync (g_Bperm)
//   K2: Z[n, k*32+o] = feat @ W  via m16n8k16 fp16 mma, fp16 output, smem-staged coalesced stores
//   K3: per-edge trilinear gather of 8 Z rows (corner pairs are contiguous 128B), fp32 combine,
//       red.global.add.v4.f32 scatter into out, deg count
//   K4: out = out / max(deg,1) + bias

#define MAXN 50176
#define KO 2048              // 64 kernels * 32 out
#define BROW_STRIDE 2056     // 2048 + 8 pad (u32) -> row stride 8224B == 32 mod 128 (bank-conflict-free B frags)
#define CPITCH 36            // C staging pitch in u32 (144B) -> conflict-free STS/LDS

__device__ __half   g_Z[(size_t)MAXN * KO];   // ~205 MB fp16 scratch
__device__ uint32_t g_Bperm[16 * KO];         // half2-packed weights: (B[2kk][c], B[2kk+1][c])
__device__ float    g_deg[MAXN];

static __device__ __forceinline__ uint32_t h2u(__half2 h) {
    return *reinterpret_cast<uint32_t*>(&h);
}

__global__ void zero_kernel(float* __restrict__ out, int n) {
    int i = blockIdx.x * blockDim.x + threadIdx.x;
    if (i < n * 32) out[i] = 0.0f;
    if (i < n) g_deg[i] = 0.0f;
}

// Bperm[kk*2048 + c] packs weight rows (2kk, 2kk+1) of column c = k*32 + o.
__global__ void prep_kernel(const float* __restrict__ w) {
    int i = blockIdx.x * blockDim.x + threadIdx.x;
    if (i >= 16 * KO) return;
    int kk = i >> 11, c = i & 2047;
    int k = c >> 5, o = c & 31;
    float w0 = w[k * 1024 + (2 * kk) * 32 + o];
    float w1 = w[k * 1024 + (2 * kk + 1) * 32 + o];
    g_Bperm[i] = h2u(__floats2half2_rn(w0, w1));
}

static __device__ __forceinline__ uint32_t lda(const float* __restrict__ f, int r, int c, int n) {
    if (r >= n) return 0u;
    float2 v = *reinterpret_cast<const float2*>(f + (size_t)r * 32 + c);
    return h2u(__floats2half2_rn(v.x, v.y));
}

// Z = feat[N,32] @ B[32,2048], fp16 out. 256 threads, 8 warps, 16 rows/warp, full B in smem.
__global__ void __launch_bounds__(256) gemm_kernel(const float* __restrict__ feat, int n) {
    extern __shared__ uint32_t smem[];
    uint32_t* sB = smem;
    for (int i = threadIdx.x; i < 16 * KO; i += blockDim.x)
        sB[(i >> 11) * BROW_STRIDE + (i & 2047)] = g_Bperm[i];
    __syncthreads();

    int warp = threadIdx.x >> 5, lane = threadIdx.x & 31;
    int g = lane >> 2, t4 = lane & 3;
    int n0 = blockIdx.x * 128 + warp * 16;
    if (n0 >= n) return;
    uint32_t* sC = smem + 16 * BROW_STRIDE + warp * (16 * CPITCH);

    int r0 = n0 + g, r1 = r0 + 8;
    uint32_t a[2][4];
#pragma unroll
    for (int ks = 0; ks < 2; ks++) {
        int c0 = ks * 16 + t4 * 2;
        a[ks][0] = lda(feat, r0, c0, n);
        a[ks][1] = lda(feat, r1, c0, n);
        a[ks][2] = lda(feat, r0, c0 + 8, n);
        a[ks][3] = lda(feat, r1, c0 + 8, n);
    }

    for (int oc = 0; oc < KO; oc += 64) {
#pragma unroll
        for (int nb = 0; nb < 8; nb++) {
            int col = oc + nb * 8 + g;
            float c0 = 0.f, c1 = 0.f, c2 = 0.f, c3 = 0.f;
#pragma unroll
            for (int ks = 0; ks < 2; ks++) {
                uint32_t b0 = sB[(ks * 8 + t4) * BROW_STRIDE + col];
                uint32_t b1 = sB[(ks * 8 + t4 + 4) * BROW_STRIDE + col];
                asm volatile(
                    "mma.sync.aligned.m16n8k16.row.col.f32.f16.f16.f32 "
                    "{%0,%1,%2,%3}, {%4,%5,%6,%7}, {%8,%9}, {%0,%1,%2,%3};"
                    : "+f"(c0), "+f"(c1), "+f"(c2), "+f"(c3)
                    : "r"(a[ks][0]), "r"(a[ks][1]), "r"(a[ks][2]), "r"(a[ks][3]),
                      "r"(b0), "r"(b1));
            }
            sC[g * CPITCH + nb * 4 + t4]       = h2u(__floats2half2_rn(c0, c1));
            sC[(g + 8) * CPITCH + nb * 4 + t4] = h2u(__floats2half2_rn(c2, c3));
        }
        __syncwarp();
#pragma unroll
        for (int p = 0; p < 4; p++) {
            int idx = p * 32 + lane;
            int ri = idx >> 3, q = idx & 7;
            int rr = n0 + ri;
            if (rr < n) {
                uint4 v = *reinterpret_cast<const uint4*>(sC + ri * CPITCH + q * 4);
                *reinterpret_cast<uint4*>(g_Z + (size_t)rr * KO + oc + q * 8) = v;
            }
        }
        __syncwarp();
    }
}

// 4 lanes per edge, each lane owns 8 output features.
__global__ void __launch_bounds__(256) edge_kernel(const float* __restrict__ pseudo,
                                                   const int* __restrict__ ei,
                                                   float* __restrict__ out, int E) {
    int t = blockIdx.x * blockDim.x + threadIdx.x;
    int e = t >> 2;
    if (e >= E) return;
    int l4 = t & 3;

    int row = ei[e];
    int col = ei[E + e];

    float v0 = pseudo[e * 3 + 0] * 3.0f;
    float v1 = pseudo[e * 3 + 1] * 3.0f;
    float v2 = pseudo[e * 3 + 2] * 3.0f;
    int b0 = (int)v0; b0 = b0 > 2 ? 2 : b0;
    int b1 = (int)v1; b1 = b1 > 2 ? 2 : b1;
    int b2 = (int)v2; b2 = b2 > 2 ? 2 : b2;
    float f0 = v0 - (float)b0, f1 = v1 - (float)b1, f2 = v2 - (float)b2;
    int base = b0 + (b1 << 2) + (b2 << 4);

    const __half* zp = g_Z + (size_t)col * KO + l4 * 8;

    float a0 = 0.f, a1 = 0.f, a2 = 0.f, a3 = 0.f, a4 = 0.f, a5 = 0.f, a6 = 0.f, a7 = 0.f;
#pragma unroll
    for (int s = 0; s < 8; s++) {
        float w = ((s & 1) ? f0 : 1.0f - f0) *
                  ((s & 2) ? f1 : 1.0f - f1) *
                  ((s & 4) ? f2 : 1.0f - f2);
        int k = base + (s & 1) + ((s & 2) << 1) + ((s & 4) << 2);
        uint4 u = *reinterpret_cast<const uint4*>(zp + (k << 5));
        float2 p0 = __half22float2(*reinterpret_cast<__half2*>(&u.x));
        float2 p1 = __half22float2(*reinterpret_cast<__half2*>(&u.y));
        float2 p2 = __half22float2(*reinterpret_cast<__half2*>(&u.z));
        float2 p3 = __half22float2(*reinterpret_cast<__half2*>(&u.w));
        a0 = fmaf(w, p0.x, a0); a1 = fmaf(w, p0.y, a1);
        a2 = fmaf(w, p1.x, a2); a3 = fmaf(w, p1.y, a3);
        a4 = fmaf(w, p2.x, a4); a5 = fmaf(w, p2.y, a5);
        a6 = fmaf(w, p3.x, a6); a7 = fmaf(w, p3.y, a7);
    }

    float* dst = out + (size_t)row * 32 + l4 * 8;
    asm volatile("red.global.add.v4.f32 [%0], {%1,%2,%3,%4};"
                 :: "l"(dst), "f"(a0), "f"(a1), "f"(a2), "f"(a3) : "memory");
    asm volatile("red.global.add.v4.f32 [%0], {%1,%2,%3,%4};"
                 :: "l"(dst + 4), "f"(a4), "f"(a5), "f"(a6), "f"(a7) : "memory");
    if (l4 == 0) atomicAdd(&g_deg[row], 1.0f);
}

__global__ void final_kernel(float* __restrict__ out, const float* __restrict__ bias, int n) {
    int i = blockIdx.x * blockDim.x + threadIdx.x;
    if (i >= n * 32) return;
    float d = g_deg[i >> 5];
    out[i] = out[i] / fmaxf(d, 1.0f) + bias[i & 31];
}

extern "C" void kernel_launch(void* const* d_in, const int* in_sizes, int n_in,
                              void* d_out, int out_size) {
    const float* feat   = (const float*)d_in[0];
    const float* pseudo = (const float*)d_in[1];
    const float* weight = (const float*)d_in[2];
    const float* bias   = (const float*)d_in[3];
    const int*   ei     = (const int*)d_in[4];
    int n = in_sizes[0] / 32;
    int E = in_sizes[4] / 2;
    float* out = (float*)d_out;

    const int smem_bytes = (16 * BROW_STRIDE + 8 * 16 * CPITCH) * 4;  // ~150 KB
    cudaFuncSetAttribute(gemm_kernel, cudaFuncAttributeMaxDynamicSharedMemorySize, smem_bytes);

    zero_kernel<<<(n * 32 + 255) / 256, 256>>>(out, n);
    prep_kernel<<<(16 * KO + 255) / 256, 256>>>(weight);
    gemm_kernel<<<(n + 127) / 128, 256, smem_bytes>>>(feat, n);
    edge_kernel<<<(E * 4 + 255) / 256, 256>>>(pseudo, ei, out, E);
    final_kernel<<<(n * 32 + 255) / 256, 256>>>(out, bias, n);
}

// round 3
// speedup vs baseline: 1.1577x; 1.1160x over previous
#include <cuda_runtime.h>
#include <cuda_fp16.h>
#include <cstdint>

// SplineGCN, round 3:
//   counting-sort edges by source node (col) -> L1-local Z gathers,
//   pre-packed 16B per-edge records, 16-warp GEMM blocks.

#define MAXN 50176            // 196 * 256
#define MAXE 1605632
#define KO 2048               // 64 kernels * 32 out
#define BROW_STRIDE 2056      // 2048 + 8 pad (u32)
#define CPITCH 36             // C staging pitch in u32

__device__ __half   g_Z[(size_t)MAXN * KO];   // ~205 MB fp16 scratch
__device__ uint32_t g_Bperm[16 * KO];
__device__ int      g_hist[MAXN];
__device__ int      g_cursor[MAXN];
__device__ int      g_part[256];
__device__ int      g_degi[MAXN];
__device__ uint4    g_rec[MAXE];              // packed sorted edge records

static __device__ __forceinline__ uint32_t h2u(__half2 h) {
    return *reinterpret_cast<uint32_t*>(&h);
}

// ---------------- zero ----------------
__global__ void zero_kernel(float* __restrict__ out, int n) {
    int i = blockIdx.x * blockDim.x + threadIdx.x;
    if (i < n * 32) out[i] = 0.0f;
    if (i < MAXN) { g_hist[i] = 0; g_degi[i] = 0; }
}

// ---------------- histogram (bin counts + degree) ----------------
__global__ void hist_kernel(const int* __restrict__ ei, int E) {
    int e = blockIdx.x * blockDim.x + threadIdx.x;
    if (e >= E) return;
    atomicAdd(&g_hist[ei[E + e]], 1);   // col bins
    atomicAdd(&g_degi[ei[e]], 1);       // row degree
}

// ---------------- two-level exclusive scan over MAXN bins ----------------
__global__ void scan1_kernel() {
    __shared__ int sh[256];
    int t = threadIdx.x, i = blockIdx.x * 256 + t;
    int v = g_hist[i];
    sh[t] = v; __syncthreads();
#pragma unroll
    for (int o = 1; o < 256; o <<= 1) {
        int u = (t >= o) ? sh[t - o] : 0;
        __syncthreads();
        sh[t] += u;
        __syncthreads();
    }
    g_cursor[i] = sh[t] - v;
    if (t == 255) g_part[blockIdx.x] = sh[255];
}
__global__ void scan2_kernel(int nb) {
    __shared__ int sh[256];
    int t = threadIdx.x;
    int v = (t < nb) ? g_part[t] : 0;
    sh[t] = v; __syncthreads();
#pragma unroll
    for (int o = 1; o < 256; o <<= 1) {
        int u = (t >= o) ? sh[t - o] : 0;
        __syncthreads();
        sh[t] += u;
        __syncthreads();
    }
    g_part[t] = sh[t] - v;
}
__global__ void scan3_kernel() {
    int i = blockIdx.x * 256 + threadIdx.x;
    g_cursor[i] += g_part[blockIdx.x];
}

// ---------------- scatter into sorted, packed records ----------------
__global__ void scatter_kernel(const float* __restrict__ pseudo,
                               const int* __restrict__ ei, int E) {
    int e = blockIdx.x * blockDim.x + threadIdx.x;
    if (e >= E) return;
    int row = ei[e];
    int col = ei[E + e];

    float v0 = pseudo[e * 3 + 0] * 3.0f;
    float v1 = pseudo[e * 3 + 1] * 3.0f;
    float v2 = pseudo[e * 3 + 2] * 3.0f;
    int b0 = (int)v0; b0 = b0 > 2 ? 2 : b0;
    int b1 = (int)v1; b1 = b1 > 2 ? 2 : b1;
    int b2 = (int)v2; b2 = b2 > 2 ? 2 : b2;
    float f0 = v0 - (float)b0, f1 = v1 - (float)b1, f2 = v2 - (float)b2;
    int base = b0 + (b1 << 2) + (b2 << 4);

    int q0 = min((int)(f0 * 65536.0f), 65535);
    int q1 = min((int)(f1 * 65536.0f), 65535);
    int q2 = min((int)(f2 * 65536.0f), 65535);

    int pos = atomicAdd(&g_cursor[col], 1);
    g_rec[pos] = make_uint4((uint32_t)row | ((uint32_t)col << 16),
                            (uint32_t)q0 | ((uint32_t)q1 << 16),
                            (uint32_t)q2 | ((uint32_t)base << 16), 0u);
}

// ---------------- weight permute ----------------
__global__ void prep_kernel(const float* __restrict__ w) {
    int i = blockIdx.x * blockDim.x + threadIdx.x;
    if (i >= 16 * KO) return;
    int kk = i >> 11, c = i & 2047;
    int k = c >> 5, o = c & 31;
    float w0 = w[k * 1024 + (2 * kk) * 32 + o];
    float w1 = w[k * 1024 + (2 * kk + 1) * 32 + o];
    g_Bperm[i] = h2u(__floats2half2_rn(w0, w1));
}

static __device__ __forceinline__ uint32_t lda(const float* __restrict__ f, int r, int c, int n) {
    if (r >= n) return 0u;
    float2 v = *reinterpret_cast<const float2*>(f + (size_t)r * 32 + c);
    return h2u(__floats2half2_rn(v.x, v.y));
}

// ---------------- Z = feat @ W (fp16 out), 16 warps / block ----------------
__global__ void __launch_bounds__(512) gemm_kernel(const float* __restrict__ feat, int n) {
    extern __shared__ uint32_t smem[];
    uint32_t* sB = smem;
    const uint4* src = reinterpret_cast<const uint4*>(g_Bperm);
    for (int i = threadIdx.x; i < 16 * KO / 4; i += blockDim.x) {
        int r = i >> 9, c4 = (i & 511) << 2;
        *reinterpret_cast<uint4*>(&sB[r * BROW_STRIDE + c4]) = src[i];
    }
    __syncthreads();

    int warp = threadIdx.x >> 5, lane = threadIdx.x & 31;
    int g = lane >> 2, t4 = lane & 3;
    int n0 = blockIdx.x * 256 + warp * 16;
    if (n0 >= n) return;
    uint32_t* sC = smem + 16 * BROW_STRIDE + warp * (16 * CPITCH);

    int r0 = n0 + g, r1 = r0 + 8;
    uint32_t a[2][4];
#pragma unroll
    for (int ks = 0; ks < 2; ks++) {
        int c0 = ks * 16 + t4 * 2;
        a[ks][0] = lda(feat, r0, c0, n);
        a[ks][1] = lda(feat, r1, c0, n);
        a[ks][2] = lda(feat, r0, c0 + 8, n);
        a[ks][3] = lda(feat, r1, c0 + 8, n);
    }

    for (int oc = 0; oc < KO; oc += 64) {
#pragma unroll
        for (int nb = 0; nb < 8; nb++) {
            int col = oc + nb * 8 + g;
            float c0 = 0.f, c1 = 0.f, c2 = 0.f, c3 = 0.f;
#pragma unroll
            for (int ks = 0; ks < 2; ks++) {
                uint32_t b0 = sB[(ks * 8 + t4) * BROW_STRIDE + col];
                uint32_t b1 = sB[(ks * 8 + t4 + 4) * BROW_STRIDE + col];
                asm volatile(
                    "mma.sync.aligned.m16n8k16.row.col.f32.f16.f16.f32 "
                    "{%0,%1,%2,%3}, {%4,%5,%6,%7}, {%8,%9}, {%0,%1,%2,%3};"
                    : "+f"(c0), "+f"(c1), "+f"(c2), "+f"(c3)
                    : "r"(a[ks][0]), "r"(a[ks][1]), "r"(a[ks][2]), "r"(a[ks][3]),
                      "r"(b0), "r"(b1));
            }
            sC[g * CPITCH + nb * 4 + t4]       = h2u(__floats2half2_rn(c0, c1));
            sC[(g + 8) * CPITCH + nb * 4 + t4] = h2u(__floats2half2_rn(c2, c3));
        }
        __syncwarp();
#pragma unroll
        for (int p = 0; p < 4; p++) {
            int idx = p * 32 + lane;
            int ri = idx >> 3, q = idx & 7;
            int rr = n0 + ri;
            if (rr < n) {
                uint4 v = *reinterpret_cast<const uint4*>(sC + ri * CPITCH + q * 4);
                *reinterpret_cast<uint4*>(g_Z + (size_t)rr * KO + oc + q * 8) = v;
            }
        }
        __syncwarp();
    }
}

// ---------------- sorted edge gather + scatter-add ----------------
__global__ void __launch_bounds__(256) edge_kernel(float* __restrict__ out, int E) {
    int t = blockIdx.x * blockDim.x + threadIdx.x;
    int e = t >> 2;
    if (e >= E) return;
    int l4 = t & 3;

    uint4 r = __ldg(&g_rec[e]);
    int row = r.x & 0xFFFF;
    int col = r.x >> 16;
    const float iq = 1.0f / 65536.0f;
    float f0 = (float)(r.y & 0xFFFF) * iq;
    float f1 = (float)(r.y >> 16) * iq;
    float f2 = (float)(r.z & 0xFFFF) * iq;
    int base = r.z >> 16;

    const __half* zp = g_Z + (size_t)col * KO + l4 * 8;

    float a0 = 0.f, a1 = 0.f, a2 = 0.f, a3 = 0.f, a4 = 0.f, a5 = 0.f, a6 = 0.f, a7 = 0.f;
#pragma unroll
    for (int s = 0; s < 8; s++) {
        float w = ((s & 1) ? f0 : 1.0f - f0) *
                  ((s & 2) ? f1 : 1.0f - f1) *
                  ((s & 4) ? f2 : 1.0f - f2);
        int k = base + (s & 1) + ((s & 2) << 1) + ((s & 4) << 2);
        uint4 u = __ldg(reinterpret_cast<const uint4*>(zp + (k << 5)));
        float2 p0 = __half22float2(*reinterpret_cast<__half2*>(&u.x));
        float2 p1 = __half22float2(*reinterpret_cast<__half2*>(&u.y));
        float2 p2 = __half22float2(*reinterpret_cast<__half2*>(&u.z));
        float2 p3 = __half22float2(*reinterpret_cast<__half2*>(&u.w));
        a0 = fmaf(w, p0.x, a0); a1 = fmaf(w, p0.y, a1);
        a2 = fmaf(w, p1.x, a2); a3 = fmaf(w, p1.y, a3);
        a4 = fmaf(w, p2.x, a4); a5 = fmaf(w, p2.y, a5);
        a6 = fmaf(w, p3.x, a6); a7 = fmaf(w, p3.y, a7);
    }

    float* dst = out + (size_t)row * 32 + l4 * 8;
    asm volatile("red.global.add.v4.f32 [%0], {%1,%2,%3,%4};"
                 :: "l"(dst), "f"(a0), "f"(a1), "f"(a2), "f"(a3) : "memory");
    asm volatile("red.global.add.v4.f32 [%0], {%1,%2,%3,%4};"
                 :: "l"(dst + 4), "f"(a4), "f"(a5), "f"(a6), "f"(a7) : "memory");
}

// ---------------- finalize ----------------
__global__ void final_kernel(float* __restrict__ out, const float* __restrict__ bias, int n) {
    int i = blockIdx.x * blockDim.x + threadIdx.x;
    if (i >= n * 32) return;
    float d = (float)g_degi[i >> 5];
    out[i] = out[i] / fmaxf(d, 1.0f) + bias[i & 31];
}

extern "C" void kernel_launch(void* const* d_in, const int* in_sizes, int n_in,
                              void* d_out, int out_size) {
    const float* feat   = (const float*)d_in[0];
    const float* pseudo = (const float*)d_in[1];
    const float* weight = (const float*)d_in[2];
    const float* bias   = (const float*)d_in[3];
    const int*   ei     = (const int*)d_in[4];
    int n = in_sizes[0] / 32;
    int E = in_sizes[4] / 2;
    float* out = (float*)d_out;

    const int nb_scan = MAXN / 256;  // 196
    const int smem_bytes = (16 * BROW_STRIDE + 16 * 16 * CPITCH) * 4;  // ~164.5 KB
    cudaFuncSetAttribute(gemm_kernel, cudaFuncAttributeMaxDynamicSharedMemorySize, smem_bytes);

    zero_kernel<<<(n * 32 + 255) / 256, 256>>>(out, n);
    hist_kernel<<<(E + 255) / 256, 256>>>(ei, E);
    scan1_kernel<<<nb_scan, 256>>>();
    scan2_kernel<<<1, 256>>>(nb_scan);
    scan3_kernel<<<nb_scan, 256>>>();
    scatter_kernel<<<(E + 255) / 256, 256>>>(pseudo, ei, E);
    prep_kernel<<<(16 * KO + 255) / 256, 256>>>(weight);
    gemm_kernel<<<(n + 255) / 256, 512, smem_bytes>>>(feat, n);
    edge_kernel<<<(E * 4 + 255) / 256, 256>>>(out, E);
    final_kernel<<<(n * 32 + 255) / 256, 256>>>(out, bias, n);
}